// round 7
// baseline (speedup 1.0000x reference)
#include <cuda_runtime.h>

// FourierKANAdapter: out[t,d] = x[t,d] + c0[d] + sum_{k=1..3} sin(kx)*cs[d,k] + cos(kx)*cc[d,k]
// T=32768, DIM=1024, K=3. coeffs layout: [DIM][7] = {c0, cs1, cc1, cs2, cc2, cs3, cc3}
//
// R6 = R5 resubmitted (previous round died on a container infra failure, not
// a kernel failure; the experiment was never run).
//
// Strategy: max occupancy, no software pipeline.
//  - ONE column per thread, 7 coeff regs. blockDim=512 covers half of DIM.
//  - __launch_bounds__(512,4): 32-reg budget -> 4 CTAs/SM = 100% occupancy.
//    Latency hiding comes from 16 warps/SMSP, not intra-thread pipelining.
//  - 4 rows front-batched per iteration (MLP_p1=4), outer loop kept rolled
//    (#pragma unroll 1) so ptxas can't hoist loads and blow the reg budget.
//  - No redundant prefetch loads. Streaming hints on x/out.

#define KAN_T    32768
#define KAN_DIM  1024
#define ROWS_PER_BLOCK 32
#define ROWS_PER_ITER  4
#define N_ITERS  (ROWS_PER_BLOCK / ROWS_PER_ITER)          // 8
#define GRID_BLOCKS ((KAN_T / ROWS_PER_BLOCK) * 2)         // 2048

__global__ __launch_bounds__(512, 4)
void fourier_kan_kernel(const float* __restrict__ x,
                        const float* __restrict__ coeffs,
                        float* __restrict__ out)
{
    const int d  = ((blockIdx.x & 1) << 9) + threadIdx.x;   // owned column
    const int t0 = (blockIdx.x >> 1) * ROWS_PER_BLOCK;      // first row

    // 7 coefficients for the single owned column.
    const float* cp = coeffs + d * 7;
    const float c0  = __ldg(cp + 0);
    const float cs1 = __ldg(cp + 1);
    const float cc1 = __ldg(cp + 2);
    const float cs2 = __ldg(cp + 3);
    const float cc2 = __ldg(cp + 4);
    const float cs3 = __ldg(cp + 5);
    const float cc3 = __ldg(cp + 6);

    const float* __restrict__ xp = x   + (size_t)t0 * KAN_DIM + d;
    float*       __restrict__ op = out + (size_t)t0 * KAN_DIM + d;

#pragma unroll 1
    for (int it = 0; it < N_ITERS; it++) {
        // Front-batched loads: 4 independent LDGs in flight before any compute.
        float v0 = __ldcs(xp + 0 * KAN_DIM);
        float v1 = __ldcs(xp + 1 * KAN_DIM);
        float v2 = __ldcs(xp + 2 * KAN_DIM);
        float v3 = __ldcs(xp + 3 * KAN_DIM);

        float r0, r1, r2, r3;
        {
            float s1, c1;
            __sincosf(v0, &s1, &c1);
            float s2 = 2.0f * s1 * c1;
            float c2 = fmaf(2.0f * c1, c1, -1.0f);
            float s3 = fmaf(s1, c2, c1 * s2);
            float c3 = fmaf(c1, c2, -s1 * s2);
            float rr = fmaf(s1, cs1, c0);
            rr = fmaf(c1, cc1, rr);
            rr = fmaf(s2, cs2, rr);
            rr = fmaf(c2, cc2, rr);
            rr = fmaf(s3, cs3, rr);
            rr = fmaf(c3, cc3, rr);
            r0 = v0 + rr;
        }
        {
            float s1, c1;
            __sincosf(v1, &s1, &c1);
            float s2 = 2.0f * s1 * c1;
            float c2 = fmaf(2.0f * c1, c1, -1.0f);
            float s3 = fmaf(s1, c2, c1 * s2);
            float c3 = fmaf(c1, c2, -s1 * s2);
            float rr = fmaf(s1, cs1, c0);
            rr = fmaf(c1, cc1, rr);
            rr = fmaf(s2, cs2, rr);
            rr = fmaf(c2, cc2, rr);
            rr = fmaf(s3, cs3, rr);
            rr = fmaf(c3, cc3, rr);
            r1 = v1 + rr;
        }
        {
            float s1, c1;
            __sincosf(v2, &s1, &c1);
            float s2 = 2.0f * s1 * c1;
            float c2 = fmaf(2.0f * c1, c1, -1.0f);
            float s3 = fmaf(s1, c2, c1 * s2);
            float c3 = fmaf(c1, c2, -s1 * s2);
            float rr = fmaf(s1, cs1, c0);
            rr = fmaf(c1, cc1, rr);
            rr = fmaf(s2, cs2, rr);
            rr = fmaf(c2, cc2, rr);
            rr = fmaf(s3, cs3, rr);
            rr = fmaf(c3, cc3, rr);
            r2 = v2 + rr;
        }
        {
            float s1, c1;
            __sincosf(v3, &s1, &c1);
            float s2 = 2.0f * s1 * c1;
            float c2 = fmaf(2.0f * c1, c1, -1.0f);
            float s3 = fmaf(s1, c2, c1 * s2);
            float c3 = fmaf(c1, c2, -s1 * s2);
            float rr = fmaf(s1, cs1, c0);
            rr = fmaf(c1, cc1, rr);
            rr = fmaf(s2, cs2, rr);
            rr = fmaf(c2, cc2, rr);
            rr = fmaf(s3, cs3, rr);
            rr = fmaf(c3, cc3, rr);
            r3 = v3 + rr;
        }

        __stcs(op + 0 * KAN_DIM, r0);
        __stcs(op + 1 * KAN_DIM, r1);
        __stcs(op + 2 * KAN_DIM, r2);
        __stcs(op + 3 * KAN_DIM, r3);

        xp += ROWS_PER_ITER * KAN_DIM;
        op += ROWS_PER_ITER * KAN_DIM;
    }
}

extern "C" void kernel_launch(void* const* d_in, const int* in_sizes, int n_in,
                              void* d_out, int out_size)
{
    const float* x      = (const float*)d_in[0];
    const float* coeffs = (const float*)d_in[1];
    float*       out    = (float*)d_out;

    fourier_kan_kernel<<<GRID_BLOCKS, 512>>>(x, coeffs, out);
}

// round 13
// speedup vs baseline: 1.0423x; 1.0423x over previous
#include <cuda_runtime.h>

// FourierKANAdapter: out[t,d] = x[t,d] + c0[d] + sum_{k=1..3} sin(kx)*cs[d,k] + cos(kx)*cc[d,k]
// T=32768, DIM=1024, K=3. coeffs layout: [DIM][7] = {c0, cs1, cc1, cs2, cc2, cs3, cc3}
//
// R12 = R8 resubmitted verbatim (two container-level infra failures; the
// persistent-grid experiment has never actually run).
//
// Strategy: chip-wide streaming ceiling (~43.5us kernel across occ 42/63/82%).
// Shave structural overheads:
//  - PERSISTENT grid: exactly 148*4 = 592 CTAs (one wave, no wave-transition
//    cost, no partial-wave tail). Each CTA grid-strides over 2-row groups.
//  - float2 access: half the LDG/STG issue count of scalar for same bytes.
//  - 2 columns/thread (14 coeff regs) + 2 rows/iter (4 x regs) keeps the
//    total under the 32-reg budget for 4 CTAs/SM.

#define KAN_T    32768
#define KAN_DIM  1024
#define ROWS_PER_G  2
#define N_GROUPS (KAN_T / ROWS_PER_G)       // 16384
#define N_CTAS   (148 * 4)                  // 592: one full wave at 4 CTA/SM

__global__ __launch_bounds__(512, 4)
void fourier_kan_kernel(const float* __restrict__ x,
                        const float* __restrict__ coeffs,
                        float* __restrict__ out)
{
    const int d = threadIdx.x * 2;          // 512 threads x float2 = 1024 = DIM

    // 7 coefficients x 2 owned columns -> 14 registers.
    float c0[2], cs1[2], cc1[2], cs2[2], cc2[2], cs3[2], cc3[2];
#pragma unroll
    for (int j = 0; j < 2; j++) {
        const float* cp = coeffs + (d + j) * 7;
        c0[j]  = __ldg(cp + 0);
        cs1[j] = __ldg(cp + 1);
        cc1[j] = __ldg(cp + 2);
        cs2[j] = __ldg(cp + 3);
        cc2[j] = __ldg(cp + 4);
        cs3[j] = __ldg(cp + 5);
        cc3[j] = __ldg(cp + 6);
    }

    // Persistent loop over 2-row groups.
#pragma unroll 1
    for (int g = blockIdx.x; g < N_GROUPS; g += N_CTAS) {
        const size_t base = (size_t)g * (ROWS_PER_G * KAN_DIM) + d;

        // Front-batched loads: 2 independent LDG.64 in flight.
        float2 v0 = __ldcs(reinterpret_cast<const float2*>(x + base));
        float2 v1 = __ldcs(reinterpret_cast<const float2*>(x + base + KAN_DIM));

        float2 o0, o1;
        {
            const float xe[2] = {v0.x, v0.y};
            float oe[2];
#pragma unroll
            for (int j = 0; j < 2; j++) {
                float s1, c1;
                __sincosf(xe[j], &s1, &c1);
                float s2 = 2.0f * s1 * c1;
                float c2 = fmaf(2.0f * c1, c1, -1.0f);
                float s3 = fmaf(s1, c2, c1 * s2);
                float c3 = fmaf(c1, c2, -s1 * s2);
                float rr = fmaf(s1, cs1[j], c0[j]);
                rr = fmaf(c1, cc1[j], rr);
                rr = fmaf(s2, cs2[j], rr);
                rr = fmaf(c2, cc2[j], rr);
                rr = fmaf(s3, cs3[j], rr);
                rr = fmaf(c3, cc3[j], rr);
                oe[j] = xe[j] + rr;
            }
            o0 = make_float2(oe[0], oe[1]);
        }
        {
            const float xe[2] = {v1.x, v1.y};
            float oe[2];
#pragma unroll
            for (int j = 0; j < 2; j++) {
                float s1, c1;
                __sincosf(xe[j], &s1, &c1);
                float s2 = 2.0f * s1 * c1;
                float c2 = fmaf(2.0f * c1, c1, -1.0f);
                float s3 = fmaf(s1, c2, c1 * s2);
                float c3 = fmaf(c1, c2, -s1 * s2);
                float rr = fmaf(s1, cs1[j], c0[j]);
                rr = fmaf(c1, cc1[j], rr);
                rr = fmaf(s2, cs2[j], rr);
                rr = fmaf(c2, cc2[j], rr);
                rr = fmaf(s3, cs3[j], rr);
                rr = fmaf(c3, cc3[j], rr);
                oe[j] = xe[j] + rr;
            }
            o1 = make_float2(oe[0], oe[1]);
        }

        __stcs(reinterpret_cast<float2*>(out + base), o0);
        __stcs(reinterpret_cast<float2*>(out + base + KAN_DIM), o1);
    }
}

extern "C" void kernel_launch(void* const* d_in, const int* in_sizes, int n_in,
                              void* d_out, int out_size)
{
    const float* x      = (const float*)d_in[0];
    const float* coeffs = (const float*)d_in[1];
    float*       out    = (float*)d_out;

    fourier_kan_kernel<<<N_CTAS, 512>>>(x, coeffs, out);
}